// round 7
// baseline (speedup 1.0000x reference)
#include <cuda_runtime.h>
#include <cstdint>

// HoyerSparsityLoss: N=1024 anchors, 1024 pos + 1024 neg targets, D=256.
// hoyer = (16 - l1/l2)/15, T=0.05. loss_i = log(sum_t exp(h/T)) - h_ii/T.
// R7: persistent snake over 1024 fine tiles (64x32) on a 444-block (3/SM) grid
// -> single wave, <=1.2% tail. Continuous cp.async chunk stream across tiles.

#define TI     64
#define TJ     32
#define DK     32
#define DVAL   256
#define NANCH  1024
#define NTILES 1024        // 16 i-tiles * 64 j-tiles (32 pos + 32 neg)
#define GRID   444         // 148 SMs * 3 resident blocks (one wave)

__device__ float    g_rowsum[NANCH];  // zero-init at load; finisher re-zeroes
__device__ float    g_diag[NANCH];
__device__ unsigned g_count;          // zero-init; finisher resets

// 1 ulp below 1.0: forces FFMA-imm (rt1); d error ~6e-8 rel, harmless.
#define C_NEG (-0.99999994f)

#define CP_ASYNC16(smem_u32, gptr) \
    asm volatile("cp.async.cg.shared.global [%0], [%1], 16;" :: "r"(smem_u32), "l"(gptr))
#define CP_COMMIT() asm volatile("cp.async.commit_group;")
#define CP_WAIT(n)  asm volatile("cp.async.wait_group %0;" :: "n"(n))

__global__ __launch_bounds__(256, 3) void hoyer_k(const float* __restrict__ anchor,
                                                  const float* __restrict__ pos,
                                                  const float* __restrict__ neg,
                                                  float* __restrict__ out) {
    __shared__ float4 As[2][8][TI];   // 16 KB
    __shared__ float4 Bs[2][8][TJ];   //  8 KB   (24 KB/block, 3/SM = 72 KB)
    __shared__ bool   s_last;

    const int tid = threadIdx.x;
    const int tx = tid & 7;               // j = tx + 8*jj, jj=0..3
    const int ty = tid >> 3;              // i = ty + 32*ii, ii=0..1

    if (tid == 0) s_last = false;

    // my tiles (snake): at most 3
    int tiles[3]; int nt = 0;
    for (int t = blockIdx.x; t < NTILES; t += GRID) tiles[nt++] = t;
    if (nt == 0) return;                  // (never for GRID<=NTILES)

    float l1[2][4], l2[2][4];
#pragma unroll
    for (int ii = 0; ii < 2; ++ii)
#pragma unroll
        for (int jj = 0; jj < 4; ++jj) { l1[ii][jj] = 0.0f; l2[ii][jj] = 0.0f; }

    auto load_chunk = [&](int t, int c, int buf) {
        const int bi = t >> 6, bjj = t & 63;
        const float* tgt = (bjj < 32) ? pos : neg;
        const int joff = (bjj & 31) * TJ;
        const int ioff = bi * TI;
#pragma unroll
        for (int r = 0; r < 2; ++r) {                    // A: 512 float4
            const int idx = tid + r * 256;
            const int row = idx & 63, c4 = idx >> 6;
            const float* ga = anchor + (size_t)(ioff + row) * DVAL + c * DK + c4 * 4;
            CP_ASYNC16((unsigned)__cvta_generic_to_shared(&As[buf][c4][row]), ga);
        }
        {                                                // B: 256 float4
            const int row = tid & 31, c4 = tid >> 5;
            const float* gb = tgt + (size_t)(joff + row) * DVAL + c * DK + c4 * 4;
            CP_ASYNC16((unsigned)__cvta_generic_to_shared(&Bs[buf][c4][row]), gb);
        }
    };

    load_chunk(tiles[0], 0, 0);
    CP_COMMIT();

    const int total = nt * 8;             // continuous chunk stream across my tiles
    for (int s = 0; s < total; ++s) {
        const int buf = s & 1;
        if (s + 1 < total) { load_chunk(tiles[(s + 1) >> 3], (s + 1) & 7, buf ^ 1);
                             CP_COMMIT(); CP_WAIT(1); }
        else               { CP_WAIT(0); }
        __syncthreads();

#pragma unroll
        for (int c4 = 0; c4 < 8; ++c4) {
            float4 bv[4];
#pragma unroll
            for (int jj = 0; jj < 4; ++jj) bv[jj] = Bs[buf][c4][tx + 8 * jj];
#pragma unroll
            for (int ii = 0; ii < 2; ++ii) {
                const float4 av = As[buf][c4][ty + 32 * ii];
                const float* af = (const float*)&av;
#pragma unroll
                for (int jj = 0; jj < 4; ++jj) {
                    const float* bf = (const float*)&bv[jj];
#pragma unroll
                    for (int dk = 0; dk < 4; ++dk) {
                        const float d = fmaf(bf[dk], C_NEG, af[dk]);   // FFMA-imm
                        l2[ii][jj] = fmaf(d, d, l2[ii][jj]);           // FFMA
                        l1[ii][jj] = fmaf(fabsf(d), 2.0f, l1[ii][jj]); // FFMA-imm
                    }
                }
            }
        }
        __syncthreads();

        if ((s & 7) == 7) {               // tile finished: epilogue + reset accum
            const int t = tiles[s >> 3];
            const int bi = t >> 6, bjj = t & 63;
            const bool is_pos = (bjj < 32);
            const int joff = (bjj & 31) * TJ;
            const int ioff = bi * TI;
            const float inv15 = 1.0f / 15.0f;
#pragma unroll
            for (int ii = 0; ii < 2; ++ii) {
                const int gi = ioff + ty + 32 * ii;
                float rsum = 0.0f;
#pragma unroll
                for (int jj = 0; jj < 4; ++jj) {
                    // l2 ~ 510; the 1e-8 eps is ~4e-10 rel -> dropped. l1 carries x2.
                    const float hy = (16.0f - l1[ii][jj] * 0.5f * rsqrtf(l2[ii][jj])) * inv15;
                    rsum += __expf(hy * 20.0f);          // hy / T, T = 0.05
                    if (is_pos && (joff + tx + 8 * jj) == gi) g_diag[gi] = hy;
                    l1[ii][jj] = 0.0f; l2[ii][jj] = 0.0f;
                }
#pragma unroll
                for (int m = 1; m < 8; m <<= 1)
                    rsum += __shfl_xor_sync(0xffffffffu, rsum, m);
                if (tx == 0) atomicAdd(&g_rowsum[gi], rsum);
            }
            __threadfence();              // release this tile's atomics/diag
            __syncthreads();
            if (tid == 0) s_last = (atomicAdd(&g_count, 1u) == NTILES - 1);
            // (fires only on the globally-last tile, which is this block's last)
        }
    }

    __syncthreads();
    if (!s_last) return;
    __threadfence();                      // acquire: all tiles' results visible

    float acc = 0.0f;
#pragma unroll
    for (int r = 0; r < 4; ++r) {
        const int i = tid + r * 256;
        acc += __logf(g_rowsum[i]) - g_diag[i] * 20.0f;
        g_rowsum[i] = 0.0f;               // reset for next graph replay
    }
#pragma unroll
    for (int m = 16; m > 0; m >>= 1) acc += __shfl_xor_sync(0xffffffffu, acc, m);

    __shared__ float warp_part[8];
    if ((tid & 31) == 0) warp_part[tid >> 5] = acc;
    __syncthreads();
    if (tid < 32) {
        float w = (tid < 8) ? warp_part[tid] : 0.0f;
#pragma unroll
        for (int m = 4; m > 0; m >>= 1) w += __shfl_xor_sync(0xffffffffu, w, m);
        if (tid == 0) { out[0] = w * (1.0f / 1024.0f); g_count = 0; }
    }
}

extern "C" void kernel_launch(void* const* d_in, const int* in_sizes, int n_in,
                              void* d_out, int out_size) {
    const float* anchor = (const float*)d_in[0];
    const float* pos    = (const float*)d_in[1];
    const float* neg    = (const float*)d_in[2];

    hoyer_k<<<GRID, 256>>>(anchor, pos, neg, (float*)d_out);
}

// round 8
// speedup vs baseline: 1.1082x; 1.1082x over previous
#include <cuda_runtime.h>
#include <cstdint>

// HoyerSparsityLoss. R8: l2 via tensor-core identity ||a-b||^2 = ||a||^2+||b||^2-2ab.
// Scalar loop computes only l1 (2x FFMA-imm rt1 per d-elem); dot via mma.sync tf32.
// Thread's l1 cells == its mma C-fragment cells -> combine in registers.

#define TI    64
#define TJ    64
#define DK    32
#define DVAL  256
#define NANCH 1024
#define NBLK  512
#define C_NEG (-0.99999994f)   // 1 ulp under 1.0 -> keeps FFMA-imm form

__device__ float    g_rowsum[NANCH];
__device__ float    g_diag[NANCH];
__device__ float    g_an[NANCH];      // ||anchor_i||^2
__device__ float    g_bn[2 * NANCH];  // ||pos_j||^2 then ||neg_j||^2
__device__ unsigned g_count;

#define CP_ASYNC16(smem_u32, gptr) \
    asm volatile("cp.async.cg.shared.global [%0], [%1], 16;" :: "r"(smem_u32), "l"(gptr))
#define CP_COMMIT() asm volatile("cp.async.commit_group;")
#define CP_WAIT(n)  asm volatile("cp.async.wait_group %0;" :: "n"(n))

__device__ __forceinline__ void mma_tf32(float c[4], uint32_t a0, uint32_t a1,
                                         uint32_t a2, uint32_t a3,
                                         uint32_t b0, uint32_t b1) {
    asm volatile("mma.sync.aligned.m16n8k8.row.col.f32.tf32.tf32.f32 "
                 "{%0,%1,%2,%3}, {%4,%5,%6,%7}, {%8,%9}, {%0,%1,%2,%3};"
                 : "+f"(c[0]), "+f"(c[1]), "+f"(c[2]), "+f"(c[3])
                 : "r"(a0), "r"(a1), "r"(a2), "r"(a3), "r"(b0), "r"(b1));
}

// Row norms: 3072 rows x 256 d. One warp per row.
__global__ __launch_bounds__(256) void norm_k(const float* __restrict__ anchor,
                                              const float* __restrict__ pos,
                                              const float* __restrict__ neg) {
    const int w = (blockIdx.x * blockDim.x + threadIdx.x) >> 5;
    const int lane = threadIdx.x & 31;
    const float* src = (w < 1024) ? anchor : ((w < 2048) ? pos : neg);
    const int row = (w < 1024) ? w : ((w < 2048) ? w - 1024 : w - 2048);
    const float4* p = (const float4*)(src + (size_t)row * DVAL);
    float acc = 0.0f;
#pragma unroll
    for (int h = 0; h < 2; ++h) {
        const float4 v = p[lane + 32 * h];
        acc += v.x * v.x + v.y * v.y + v.z * v.z + v.w * v.w;
    }
#pragma unroll
    for (int m = 16; m > 0; m >>= 1) acc += __shfl_xor_sync(0xffffffffu, acc, m);
    if (lane == 0) { if (w < 1024) g_an[w] = acc; else g_bn[w - 1024] = acc; }
}

__global__ __launch_bounds__(256, 2) void hoyer_k(const float* __restrict__ anchor,
                                                  const float* __restrict__ pos,
                                                  const float* __restrict__ neg,
                                                  float* __restrict__ out) {
    __shared__ float4 As[2][8][TI];   // 16 KB
    __shared__ float4 Bs[2][8][TJ];   // 16 KB

    const int bi = blockIdx.x;             // 16 i-tiles
    const int bj = blockIdx.y;             // 32 j-tiles
    const bool is_pos = (bj < 16);
    const float* tgt = is_pos ? pos : neg;
    const int joff = (is_pos ? bj : bj - 16) * TJ;
    const int ioff = bi * TI;
    const int tid  = threadIdx.x;
    const int warp = tid >> 5, lane = tid & 31;
    const int rb = warp >> 1;              // row-block: rows 16rb..16rb+15
    const int cbase = (warp & 1) * 4;      // col-blocks cbase..cbase+3 (8 cols each)
    const int g = lane >> 2, q = lane & 3; // fragment coords

    float l1[2][8];                        // [r2][2*cb2+jj2], rows g(+8), cols 2q(+1)
    float cf[4][4];                        // mma C frags per cb2
#pragma unroll
    for (int r2 = 0; r2 < 2; ++r2)
#pragma unroll
        for (int k = 0; k < 8; ++k) l1[r2][k] = 0.0f;
#pragma unroll
    for (int cb2 = 0; cb2 < 4; ++cb2)
#pragma unroll
        for (int k = 0; k < 4; ++k) cf[cb2][k] = 0.0f;

    auto load_chunk = [&](int c, int buf) {
#pragma unroll
        for (int r = 0; r < 2; ++r) {
            const int idx = tid + r * 256;
            const int row = idx & 63, c4 = idx >> 6;
            const float* ga = anchor + (size_t)(ioff + row) * DVAL + c * DK + c4 * 4;
            CP_ASYNC16((unsigned)__cvta_generic_to_shared(&As[buf][c4][row]), ga);
            const float* gb = tgt + (size_t)(joff + row) * DVAL + c * DK + c4 * 4;
            CP_ASYNC16((unsigned)__cvta_generic_to_shared(&Bs[buf][c4][row]), gb);
        }
    };

    load_chunk(0, 0);
    CP_COMMIT();

    for (int c = 0; c < DVAL / DK; ++c) {
        const int buf = c & 1;
        if (c + 1 < 8) { load_chunk(c + 1, buf ^ 1); CP_COMMIT(); CP_WAIT(1); }
        else           { CP_WAIT(0); }
        __syncthreads();

#pragma unroll
        for (int ks = 0; ks < 4; ++ks) {           // k-step = 8 d (two c4 groups)
            const int c40 = 2 * ks, c41 = 2 * ks + 1;
            // A fragment (row-major m16k8), lane-linear LDS.32
            const uint32_t a0 = __float_as_uint(((const float*)&As[buf][c40][16*rb + g    ])[q]);
            const uint32_t a1 = __float_as_uint(((const float*)&As[buf][c40][16*rb + g + 8])[q]);
            const uint32_t a2 = __float_as_uint(((const float*)&As[buf][c41][16*rb + g    ])[q]);
            const uint32_t a3 = __float_as_uint(((const float*)&As[buf][c41][16*rb + g + 8])[q]);
            // A rows for l1 (float4 per c4)
            float4 ar[2][2];
#pragma unroll
            for (int r2 = 0; r2 < 2; ++r2) {
                ar[r2][0] = As[buf][c40][16*rb + g + 8*r2];
                ar[r2][1] = As[buf][c41][16*rb + g + 8*r2];
            }
#pragma unroll
            for (int cb2 = 0; cb2 < 4; ++cb2) {
                const int cb = cbase + cb2;
                // B fragment (col-major k8n8)
                const uint32_t b0 = __float_as_uint(((const float*)&Bs[buf][c40][8*cb + g])[q]);
                const uint32_t b1 = __float_as_uint(((const float*)&Bs[buf][c41][8*cb + g])[q]);
                mma_tf32(cf[cb2], a0, a1, a2, a3, b0, b1);
                // l1 for the matching cells: j = 8cb + 2q + jj2
#pragma unroll
                for (int jj2 = 0; jj2 < 2; ++jj2) {
                    const float4 bj0 = Bs[buf][c40][8*cb + 2*q + jj2];
                    const float4 bj1 = Bs[buf][c41][8*cb + 2*q + jj2];
                    const float* b0f = (const float*)&bj0;
                    const float* b1f = (const float*)&bj1;
#pragma unroll
                    for (int r2 = 0; r2 < 2; ++r2) {
                        const float* a0f = (const float*)&ar[r2][0];
                        const float* a1f = (const float*)&ar[r2][1];
                        float acc = l1[r2][2*cb2 + jj2];
#pragma unroll
                        for (int dk = 0; dk < 4; ++dk) {
                            const float d0 = fmaf(b0f[dk], C_NEG, a0f[dk]);  // FFMA-imm
                            acc = fmaf(fabsf(d0), 2.0f, acc);                // FFMA-imm
                            const float d1 = fmaf(b1f[dk], C_NEG, a1f[dk]);
                            acc = fmaf(fabsf(d1), 2.0f, acc);
                        }
                        l1[r2][2*cb2 + jj2] = acc;
                    }
                }
            }
        }
        __syncthreads();
    }

    // Epilogue: l2 from norms + dot; hoyer -> exp -> row sums.
    const float inv15 = 1.0f / 15.0f;
    const float* bn = g_bn + (is_pos ? 0 : NANCH);
#pragma unroll
    for (int r2 = 0; r2 < 2; ++r2) {
        const int gi = ioff + 16*rb + g + 8*r2;
        const float an_i = g_an[gi];
        float rsum = 0.0f;
#pragma unroll
        for (int cb2 = 0; cb2 < 4; ++cb2) {
#pragma unroll
            for (int jj2 = 0; jj2 < 2; ++jj2) {
                const int jl = 8*(cbase + cb2) + 2*q + jj2;
                const int gj = joff + jl;
                const float dot = cf[cb2][2*r2 + jj2];
                const float l2sq = an_i + bn[gj] - 2.0f * dot;   // ~510, no cancellation
                const float hy = (16.0f - l1[r2][2*cb2 + jj2] * 0.5f * rsqrtf(l2sq)) * inv15;
                rsum += __expf(hy * 20.0f);      // hy / T, T = 0.05
                if (is_pos && gj == gi) g_diag[gi] = hy;
            }
        }
        // reduce over the 4 lanes sharing this row (lanes 4g..4g+3)
        rsum += __shfl_xor_sync(0xffffffffu, rsum, 1);
        rsum += __shfl_xor_sync(0xffffffffu, rsum, 2);
        if (q == 0) atomicAdd(&g_rowsum[gi], rsum);
    }

    // ---- last-block final reduction ----
    __shared__ bool is_last;
    __threadfence();
    if (tid == 0) is_last = (atomicAdd(&g_count, 1u) == NBLK - 1);
    __syncthreads();
    if (!is_last) return;
    __threadfence();

    float acc = 0.0f;
#pragma unroll
    for (int r = 0; r < 4; ++r) {
        const int i = tid + r * 256;
        acc += __logf(g_rowsum[i]) - g_diag[i] * 20.0f;
        g_rowsum[i] = 0.0f;               // reset for next graph replay
    }
#pragma unroll
    for (int m = 16; m > 0; m >>= 1) acc += __shfl_xor_sync(0xffffffffu, acc, m);

    __shared__ float warp_part[8];
    if ((tid & 31) == 0) warp_part[tid >> 5] = acc;
    __syncthreads();
    if (tid < 32) {
        float w = (tid < 8) ? warp_part[tid] : 0.0f;
#pragma unroll
        for (int m = 4; m > 0; m >>= 1) w += __shfl_xor_sync(0xffffffffu, w, m);
        if (tid == 0) { out[0] = w * (1.0f / 1024.0f); g_count = 0; }
    }
}

extern "C" void kernel_launch(void* const* d_in, const int* in_sizes, int n_in,
                              void* d_out, int out_size) {
    const float* anchor = (const float*)d_in[0];
    const float* pos    = (const float*)d_in[1];
    const float* neg    = (const float*)d_in[2];

    norm_k<<<384, 256>>>(anchor, pos, neg);           // 3072 warps, one per row
    dim3 grid(NANCH / TI, 32);
    hoyer_k<<<grid, 256>>>(anchor, pos, neg, (float*)d_out);
}

// round 9
// speedup vs baseline: 1.1321x; 1.0215x over previous
#include <cuda_runtime.h>
#include <cstdint>

// HoyerSparsityLoss. R9: l1 via R5-style scalar tiling (2x FFMA-imm rt1 /elem,
// 16 FFMA per LDS); dot via mma.sync tf32 in fragment layout; the two meet
// through a padded smem dot-exchange at epilogue. l2^2 = |a|^2+|b|^2-2ab.

#define TI    64
#define TJ    64
#define DK    32
#define DVAL  256
#define NANCH 1024
#define NBLK  512
#define C_NEG (-0.99999994f)   // 1 ulp under 1.0 -> keeps FFMA-imm form
#define DSTR  72               // dot smem row stride (pad vs 64 -> <=2-way conflicts)

__device__ float    g_rowsum[NANCH];
__device__ float    g_diag[NANCH];
__device__ float    g_an[NANCH];      // ||anchor_i||^2
__device__ float    g_bn[2 * NANCH];  // ||pos_j||^2 then ||neg_j||^2
__device__ unsigned g_count;

#define CP_ASYNC16(smem_u32, gptr) \
    asm volatile("cp.async.cg.shared.global [%0], [%1], 16;" :: "r"(smem_u32), "l"(gptr))
#define CP_COMMIT() asm volatile("cp.async.commit_group;")
#define CP_WAIT(n)  asm volatile("cp.async.wait_group %0;" :: "n"(n))

__device__ __forceinline__ void mma_tf32(float c[4], uint32_t a0, uint32_t a1,
                                         uint32_t a2, uint32_t a3,
                                         uint32_t b0, uint32_t b1) {
    asm volatile("mma.sync.aligned.m16n8k8.row.col.f32.tf32.tf32.f32 "
                 "{%0,%1,%2,%3}, {%4,%5,%6,%7}, {%8,%9}, {%0,%1,%2,%3};"
                 : "+f"(c[0]), "+f"(c[1]), "+f"(c[2]), "+f"(c[3])
                 : "r"(a0), "r"(a1), "r"(a2), "r"(a3), "r"(b0), "r"(b1));
}

// Row norms: 3072 rows x 256 d; one warp per row.
__global__ __launch_bounds__(256) void norm_k(const float* __restrict__ anchor,
                                              const float* __restrict__ pos,
                                              const float* __restrict__ neg) {
    const int w = (blockIdx.x * blockDim.x + threadIdx.x) >> 5;
    const int lane = threadIdx.x & 31;
    const float* src = (w < 1024) ? anchor : ((w < 2048) ? pos : neg);
    const int row = (w < 1024) ? w : ((w < 2048) ? w - 1024 : w - 2048);
    const float4* p = (const float4*)(src + (size_t)row * DVAL);
    float acc = 0.0f;
#pragma unroll
    for (int h = 0; h < 2; ++h) {
        const float4 v = p[lane + 32 * h];
        acc += v.x * v.x + v.y * v.y + v.z * v.z + v.w * v.w;
    }
#pragma unroll
    for (int m = 16; m > 0; m >>= 1) acc += __shfl_xor_sync(0xffffffffu, acc, m);
    if (lane == 0) { if (w < 1024) g_an[w] = acc; else g_bn[w - 1024] = acc; }
}

union SmemU {
    struct { float4 As[2][8][TI]; float4 Bs[2][8][TJ]; } t;   // 32 KB
    float dot[64 * DSTR];                                     // 18 KB (aliased)
};

__global__ __launch_bounds__(256, 2) void hoyer_k(const float* __restrict__ anchor,
                                                  const float* __restrict__ pos,
                                                  const float* __restrict__ neg,
                                                  float* __restrict__ out) {
    __shared__ SmemU sm;

    const int bi = blockIdx.x;             // 16 i-tiles
    const int bj = blockIdx.y;             // 32 j-tiles
    const bool is_pos = (bj < 16);
    const float* tgt = is_pos ? pos : neg;
    const int joff = (is_pos ? bj : bj - 16) * TJ;
    const int ioff = bi * TI;
    const int tid  = threadIdx.x;
    // l1 tiling (R5): i = ty + 16*ii, j = tx + 16*jj
    const int tx = tid & 15, ty = tid >> 4;
    // mma tiling: warp rb covers rows 16rb.., cbase covers 32 cols
    const int warp = tid >> 5, lane = tid & 31;
    const int rb = warp >> 1, cbase = (warp & 1) * 4;
    const int g = lane >> 2, q = lane & 3;

    float l1[4][4];
    float cf[4][4];
#pragma unroll
    for (int a = 0; a < 4; ++a)
#pragma unroll
        for (int b = 0; b < 4; ++b) { l1[a][b] = 0.0f; cf[a][b] = 0.0f; }

    auto load_chunk = [&](int c, int buf) {
#pragma unroll
        for (int r = 0; r < 2; ++r) {
            const int idx = tid + r * 256;
            const int row = idx & 63, c4 = idx >> 6;
            const float* ga = anchor + (size_t)(ioff + row) * DVAL + c * DK + c4 * 4;
            CP_ASYNC16((unsigned)__cvta_generic_to_shared(&sm.t.As[buf][c4][row]), ga);
            const float* gb = tgt + (size_t)(joff + row) * DVAL + c * DK + c4 * 4;
            CP_ASYNC16((unsigned)__cvta_generic_to_shared(&sm.t.Bs[buf][c4][row]), gb);
        }
    };

    load_chunk(0, 0);
    CP_COMMIT();

    for (int c = 0; c < DVAL / DK; ++c) {
        const int buf = c & 1;
        if (c + 1 < 8) { load_chunk(c + 1, buf ^ 1); CP_COMMIT(); CP_WAIT(1); }
        else           { CP_WAIT(0); }
        __syncthreads();

        // ---- phase 1: l1 (R5 layout, 16 FFMA per LDS, all FFMA-imm rt1) ----
#pragma unroll
        for (int c4 = 0; c4 < 8; ++c4) {
            float4 bv[4];
#pragma unroll
            for (int jj = 0; jj < 4; ++jj) bv[jj] = sm.t.Bs[buf][c4][tx + 16 * jj];
#pragma unroll
            for (int ii = 0; ii < 4; ++ii) {
                const float4 av = sm.t.As[buf][c4][ty + 16 * ii];
                const float* af = (const float*)&av;
#pragma unroll
                for (int jj = 0; jj < 4; ++jj) {
                    const float* bf = (const float*)&bv[jj];
#pragma unroll
                    for (int dk = 0; dk < 4; ++dk) {
                        const float d = fmaf(bf[dk], C_NEG, af[dk]);   // FFMA-imm
                        l1[ii][jj] = fmaf(fabsf(d), 2.0f, l1[ii][jj]); // FFMA-imm
                    }
                }
            }
        }

        // ---- phase 2: dot via mma.sync tf32 (fragment layout) ----
#pragma unroll
        for (int ks = 0; ks < 4; ++ks) {
            const int c40 = 2 * ks, c41 = 2 * ks + 1;
            const uint32_t a0 = __float_as_uint(((const float*)&sm.t.As[buf][c40][16*rb + g    ])[q]);
            const uint32_t a1 = __float_as_uint(((const float*)&sm.t.As[buf][c40][16*rb + g + 8])[q]);
            const uint32_t a2 = __float_as_uint(((const float*)&sm.t.As[buf][c41][16*rb + g    ])[q]);
            const uint32_t a3 = __float_as_uint(((const float*)&sm.t.As[buf][c41][16*rb + g + 8])[q]);
#pragma unroll
            for (int cb2 = 0; cb2 < 4; ++cb2) {
                const int cb = cbase + cb2;
                const uint32_t b0 = __float_as_uint(((const float*)&sm.t.Bs[buf][c40][8*cb + g])[q]);
                const uint32_t b1 = __float_as_uint(((const float*)&sm.t.Bs[buf][c41][8*cb + g])[q]);
                mma_tf32(cf[cb2], a0, a1, a2, a3, b0, b1);
            }
        }
        __syncthreads();
    }

    // ---- dot exchange: fragments -> sm.dot (aliases As/Bs; all reads done) ----
#pragma unroll
    for (int cb2 = 0; cb2 < 4; ++cb2)
#pragma unroll
        for (int r2 = 0; r2 < 2; ++r2)
#pragma unroll
            for (int jj2 = 0; jj2 < 2; ++jj2)
                sm.dot[(16*rb + g + 8*r2) * DSTR + 8*(cbase + cb2) + 2*q + jj2] =
                    cf[cb2][2*r2 + jj2];
    __syncthreads();

    // ---- epilogue: l2 from norms + dot; hoyer -> exp -> row sums ----
    const float inv15 = 1.0f / 15.0f;
    const float* bn = g_bn + (is_pos ? 0 : NANCH);
#pragma unroll
    for (int ii = 0; ii < 4; ++ii) {
        const int gi = ioff + ty + 16 * ii;
        const float an_i = g_an[gi];
        float rsum = 0.0f;
#pragma unroll
        for (int jj = 0; jj < 4; ++jj) {
            const int gj = joff + tx + 16 * jj;
            const float dot = sm.dot[(ty + 16*ii) * DSTR + tx + 16*jj];
            const float l2sq = an_i + bn[gj] - 2.0f * dot;   // ~510, no cancellation
            // l1 carries x2 -> *0.5. eps 1e-8 is ~4e-10 rel -> dropped.
            const float hy = (16.0f - l1[ii][jj] * 0.5f * rsqrtf(l2sq)) * inv15;
            rsum += __expf(hy * 20.0f);      // hy / T, T = 0.05
            if (is_pos && gj == gi) g_diag[gi] = hy;
        }
#pragma unroll
        for (int m = 1; m < 16; m <<= 1)
            rsum += __shfl_xor_sync(0xffffffffu, rsum, m);
        if (tx == 0) atomicAdd(&g_rowsum[gi], rsum);
    }

    // ---- last-block final reduction ----
    __shared__ bool is_last;
    __threadfence();
    if (tid == 0) is_last = (atomicAdd(&g_count, 1u) == NBLK - 1);
    __syncthreads();
    if (!is_last) return;
    __threadfence();

    float acc = 0.0f;
#pragma unroll
    for (int r = 0; r < 4; ++r) {
        const int i = tid + r * 256;
        acc += __logf(g_rowsum[i]) - g_diag[i] * 20.0f;
        g_rowsum[i] = 0.0f;               // reset for next graph replay
    }
#pragma unroll
    for (int m = 16; m > 0; m >>= 1) acc += __shfl_xor_sync(0xffffffffu, acc, m);

    __shared__ float warp_part[8];
    if ((tid & 31) == 0) warp_part[tid >> 5] = acc;
    __syncthreads();
    if (tid < 32) {
        float w = (tid < 8) ? warp_part[tid] : 0.0f;
#pragma unroll
        for (int m = 4; m > 0; m >>= 1) w += __shfl_xor_sync(0xffffffffu, w, m);
        if (tid == 0) { out[0] = w * (1.0f / 1024.0f); g_count = 0; }
    }
}

extern "C" void kernel_launch(void* const* d_in, const int* in_sizes, int n_in,
                              void* d_out, int out_size) {
    const float* anchor = (const float*)d_in[0];
    const float* pos    = (const float*)d_in[1];
    const float* neg    = (const float*)d_in[2];

    norm_k<<<384, 256>>>(anchor, pos, neg);
    dim3 grid(NANCH / TI, 32);
    hoyer_k<<<grid, 256>>>(anchor, pos, neg, (float*)d_out);
}

// round 12
// speedup vs baseline: 1.1362x; 1.0036x over previous
#include <cuda_runtime.h>
#include <cstdint>

// HoyerSparsityLoss. R11 = R10 with the 48KB smem overflow fixed (epilogue
// scratch folded into the union). l1 scalar (2x FFMA-imm/elem) + dot via
// mma.sync tf32; l2^2 = |a|^2+|b|^2-2ab. 3-stage cp.async ring, ONE barrier
// per chunk, mma interleaved into the FFMA stream.

#define TI    64
#define TJ    64
#define DK    32
#define DVAL  256
#define NANCH 1024
#define NBLK  512
#define C_NEG (-0.99999994f)   // 1 ulp under 1.0 -> keeps FFMA-imm form
#define DSTR  72               // dot smem row stride (pad -> <=2-way conflicts)

__device__ float    g_rowsum[NANCH];
__device__ float    g_diag[NANCH];
__device__ float    g_an[NANCH];      // ||anchor_i||^2
__device__ float    g_bn[2 * NANCH];  // ||pos_j||^2 then ||neg_j||^2
__device__ unsigned g_count;

#define CP_ASYNC16(smem_u32, gptr) \
    asm volatile("cp.async.cg.shared.global [%0], [%1], 16;" :: "r"(smem_u32), "l"(gptr))
#define CP_COMMIT() asm volatile("cp.async.commit_group;")
#define CP_WAIT(n)  asm volatile("cp.async.wait_group %0;" :: "n"(n))

__device__ __forceinline__ void mma_tf32(float c[4], uint32_t a0, uint32_t a1,
                                         uint32_t a2, uint32_t a3,
                                         uint32_t b0, uint32_t b1) {
    asm volatile("mma.sync.aligned.m16n8k8.row.col.f32.tf32.tf32.f32 "
                 "{%0,%1,%2,%3}, {%4,%5,%6,%7}, {%8,%9}, {%0,%1,%2,%3};"
                 : "+f"(c[0]), "+f"(c[1]), "+f"(c[2]), "+f"(c[3])
                 : "r"(a0), "r"(a1), "r"(a2), "r"(a3), "r"(b0), "r"(b1));
}

__global__ __launch_bounds__(256) void norm_k(const float* __restrict__ anchor,
                                              const float* __restrict__ pos,
                                              const float* __restrict__ neg) {
    const int w = (blockIdx.x * blockDim.x + threadIdx.x) >> 5;
    const int lane = threadIdx.x & 31;
    const float* src = (w < 1024) ? anchor : ((w < 2048) ? pos : neg);
    const int row = (w < 1024) ? w : ((w < 2048) ? w - 1024 : w - 2048);
    const float4* p = (const float4*)(src + (size_t)row * DVAL);
    float acc = 0.0f;
#pragma unroll
    for (int h = 0; h < 2; ++h) {
        const float4 v = p[lane + 32 * h];
        acc += v.x * v.x + v.y * v.y + v.z * v.z + v.w * v.w;
    }
#pragma unroll
    for (int m = 16; m > 0; m >>= 1) acc += __shfl_xor_sync(0xffffffffu, acc, m);
    if (lane == 0) { if (w < 1024) g_an[w] = acc; else g_bn[w - 1024] = acc; }
}

struct Stage { float4 A[8][TI]; float4 B[8][TJ]; };   // 16 KB
union SmemU {
    Stage st[3];                 // 48 KB ring
    struct {                     // epilogue overlay (ring dead by then)
        float dot[64 * DSTR];    // 18 KB
        float warp_part[8];
        int   is_last;
    } e;
};

__global__ __launch_bounds__(256, 2) void hoyer_k(const float* __restrict__ anchor,
                                                  const float* __restrict__ pos,
                                                  const float* __restrict__ neg,
                                                  float* __restrict__ out) {
    __shared__ SmemU sm;

    const int bi = blockIdx.x;             // 16 i-tiles
    const int bj = blockIdx.y;             // 32 j-tiles
    const bool is_pos = (bj < 16);
    const float* tgt = is_pos ? pos : neg;
    const int joff = (is_pos ? bj : bj - 16) * TJ;
    const int ioff = bi * TI;
    const int tid  = threadIdx.x;
    const int tx = tid & 15, ty = tid >> 4;          // l1 tiling
    const int warp = tid >> 5, lane = tid & 31;      // mma tiling
    const int rb = warp >> 1, cbase = (warp & 1) * 4;
    const int g = lane >> 2, q = lane & 3;

    float l1[4][4], cf[4][4];
#pragma unroll
    for (int a = 0; a < 4; ++a)
#pragma unroll
        for (int b = 0; b < 4; ++b) { l1[a][b] = 0.0f; cf[a][b] = 0.0f; }

    auto load_chunk = [&](int c, int s) {
#pragma unroll
        for (int r = 0; r < 2; ++r) {
            const int idx = tid + r * 256;
            const int row = idx & 63, c4 = idx >> 6;
            const float* ga = anchor + (size_t)(ioff + row) * DVAL + c * DK + c4 * 4;
            CP_ASYNC16((unsigned)__cvta_generic_to_shared(&sm.st[s].A[c4][row]), ga);
            const float* gb = tgt + (size_t)(joff + row) * DVAL + c * DK + c4 * 4;
            CP_ASYNC16((unsigned)__cvta_generic_to_shared(&sm.st[s].B[c4][row]), gb);
        }
    };

    load_chunk(0, 0); CP_COMMIT();
    load_chunk(1, 1); CP_COMMIT();

    for (int c = 0; c < DVAL / DK; ++c) {
        const int s = c % 3;
        if (c < 7) CP_WAIT(1); else CP_WAIT(0);
        __syncthreads();                       // single barrier per chunk
        if (c + 2 < 8) { load_chunk(c + 2, (c + 2) % 3); CP_COMMIT(); }
        // refill stage (c+2)%3 == (c-1)%3, whose last read preceded this barrier

#pragma unroll
        for (int ks = 0; ks < 4; ++ks) {
            const int c40 = 2 * ks, c41 = 2 * ks + 1;
            // ---- l1 for c40,c41: independent FFMA-imm stream ----
#pragma unroll
            for (int h = 0; h < 2; ++h) {
                const int c4 = 2 * ks + h;
                float4 bv[4];
#pragma unroll
                for (int jj = 0; jj < 4; ++jj) bv[jj] = sm.st[s].B[c4][tx + 16 * jj];
#pragma unroll
                for (int ii = 0; ii < 4; ++ii) {
                    const float4 av = sm.st[s].A[c4][ty + 16 * ii];
                    const float* af = (const float*)&av;
#pragma unroll
                    for (int jj = 0; jj < 4; ++jj) {
                        const float* bf = (const float*)&bv[jj];
#pragma unroll
                        for (int dk = 0; dk < 4; ++dk) {
                            const float d = fmaf(bf[dk], C_NEG, af[dk]);   // FFMA-imm
                            l1[ii][jj] = fmaf(fabsf(d), 2.0f, l1[ii][jj]); // FFMA-imm
                        }
                    }
                }
            }
            // ---- mma k8 step, latency covered by the FFMA stream ----
            const uint32_t a0 = __float_as_uint(((const float*)&sm.st[s].A[c40][16*rb + g    ])[q]);
            const uint32_t a1 = __float_as_uint(((const float*)&sm.st[s].A[c40][16*rb + g + 8])[q]);
            const uint32_t a2 = __float_as_uint(((const float*)&sm.st[s].A[c41][16*rb + g    ])[q]);
            const uint32_t a3 = __float_as_uint(((const float*)&sm.st[s].A[c41][16*rb + g + 8])[q]);
#pragma unroll
            for (int cb2 = 0; cb2 < 4; ++cb2) {
                const int cb = cbase + cb2;
                const uint32_t b0 = __float_as_uint(((const float*)&sm.st[s].B[c40][8*cb + g])[q]);
                const uint32_t b1 = __float_as_uint(((const float*)&sm.st[s].B[c41][8*cb + g])[q]);
                mma_tf32(cf[cb2], a0, a1, a2, a3, b0, b1);
            }
        }
    }

    // ---- dot exchange (overlay aliases the ring; all ring reads done) ----
    __syncthreads();
#pragma unroll
    for (int cb2 = 0; cb2 < 4; ++cb2)
#pragma unroll
        for (int r2 = 0; r2 < 2; ++r2)
#pragma unroll
            for (int jj2 = 0; jj2 < 2; ++jj2)
                sm.e.dot[(16*rb + g + 8*r2) * DSTR + 8*(cbase + cb2) + 2*q + jj2] =
                    cf[cb2][2*r2 + jj2];
    __syncthreads();

    // ---- epilogue: l2 from norms + dot; hoyer -> exp -> row sums ----
    const float inv15 = 1.0f / 15.0f;
    const float* bn = g_bn + (is_pos ? 0 : NANCH);
#pragma unroll
    for (int ii = 0; ii < 4; ++ii) {
        const int gi = ioff + ty + 16 * ii;
        const float an_i = g_an[gi];
        float rsum = 0.0f;
#pragma unroll
        for (int jj = 0; jj < 4; ++jj) {
            const int gj = joff + tx + 16 * jj;
            const float dot = sm.e.dot[(ty + 16*ii) * DSTR + tx + 16*jj];
            const float l2sq = an_i + bn[gj] - 2.0f * dot;   // ~510, no cancellation
            const float hy = (16.0f - l1[ii][jj] * 0.5f * rsqrtf(l2sq)) * inv15;
            rsum += __expf(hy * 20.0f);      // hy / T, T = 0.05
            if (is_pos && gj == gi) g_diag[gi] = hy;
        }
#pragma unroll
        for (int m = 1; m < 16; m <<= 1)
            rsum += __shfl_xor_sync(0xffffffffu, rsum, m);
        if (tx == 0) atomicAdd(&g_rowsum[gi], rsum);
    }

    // ---- last-block final reduction ----
    __threadfence();
    if (tid == 0) sm.e.is_last = (atomicAdd(&g_count, 1u) == NBLK - 1) ? 1 : 0;
    __syncthreads();
    if (!sm.e.is_last) return;
    __threadfence();

    float acc = 0.0f;
#pragma unroll
    for (int r = 0; r < 4; ++r) {
        const int i = tid + r * 256;
        acc += __logf(g_rowsum[i]) - g_diag[i] * 20.0f;
        g_rowsum[i] = 0.0f;               // reset for next graph replay
    }
#pragma unroll
    for (int m = 16; m > 0; m >>= 1) acc += __shfl_xor_sync(0xffffffffu, acc, m);

    if ((tid & 31) == 0) sm.e.warp_part[tid >> 5] = acc;
    __syncthreads();
    if (tid < 32) {
        float w = (tid < 8) ? sm.e.warp_part[tid] : 0.0f;
#pragma unroll
        for (int m = 4; m > 0; m >>= 1) w += __shfl_xor_sync(0xffffffffu, w, m);
        if (tid == 0) { out[0] = w * (1.0f / 1024.0f); g_count = 0; }
    }
}

extern "C" void kernel_launch(void* const* d_in, const int* in_sizes, int n_in,
                              void* d_out, int out_size) {
    const float* anchor = (const float*)d_in[0];
    const float* pos    = (const float*)d_in[1];
    const float* neg    = (const float*)d_in[2];

    norm_k<<<384, 256>>>(anchor, pos, neg);
    dim3 grid(NANCH / TI, 32);
    hoyer_k<<<grid, 256>>>(anchor, pos, neg, (float*)d_out);
}